// round 1
// baseline (speedup 1.0000x reference)
#include <cuda_runtime.h>
#include <math.h>

#define B_N    8192
#define K_N    512
#define D_N    2048
#define Q_N    8
#define NCOL   4608            // 512 (pm) + 512*8 (PinvW)
#define LOG2PI 1.8378770664093453f
#define EPSC   1e-5f

// ---------------- scratch (static __device__, no allocation) ----------------
__device__ float  g_Wcat[(size_t)D_N * NCOL];   // [d][n] row-major, 37.7 MB
__device__ float  g_C[(size_t)B_N * NCOL];      // GEMM out / scores, 151 MB
__device__ float  g_psi_inv[D_N];
__device__ float  g_logdetPsi;
__device__ float  g_r[B_N];                     // x^T Psi^-1 x
__device__ float  g_wpm[K_N * Q_N];             // W^T Psi^-1 mu
__device__ float  g_Minv[K_N * 64];             // full 8x8 M^-1 per k
__device__ float  g_logdetM[K_N];
__device__ float  g_mumu[K_N];                  // mu^T Psi^-1 mu
__device__ float  g_off[K_N];                   // per-k constant offset
__device__ double g_acc;                        // NLL accumulator

__device__ __forceinline__ float softplusf(float x) {
    return x > 20.0f ? x : log1pf(expf(x));
}

// ---------------- psi precompute ----------------
__global__ void k_psi(const float* __restrict__ psi_rho) {
    __shared__ float ssum;
    int tid = threadIdx.x;
    if (tid == 0) ssum = 0.0f;
    __syncthreads();
    float l = 0.0f;
    for (int d = tid; d < D_N; d += 256) {
        float p = softplusf(psi_rho[d]) + EPSC;
        g_psi_inv[d] = 1.0f / p;
        l += logf(p);
    }
    atomicAdd(&ssum, l);
    __syncthreads();
    if (tid == 0) g_logdetPsi = ssum;
}

// ---------------- per-component precompute (one block per k) ----------------
__global__ void prep_k(const float* __restrict__ dir_raw,
                       const float* __restrict__ mu,
                       const float* __restrict__ scale_rho) {
    int k   = blockIdx.x;
    int tid = threadIdx.x;
    __shared__ float s_nsq[8];
    __shared__ float s_alpha[8];
    __shared__ float s_acc[45];   // 36 (lower-tri S) + 8 (wm) + 1 (mumu)
    if (tid < 8)  s_nsq[tid] = 0.0f;
    if (tid < 45) s_acc[tid] = 0.0f;
    __syncthreads();

    const float* dirk = dir_raw + (size_t)k * D_N * Q_N;
    const float* muk  = mu + (size_t)k * D_N;

    // pass 1: column norms over D
    float ns[8];
#pragma unroll
    for (int j = 0; j < 8; j++) ns[j] = 0.0f;
    for (int d = tid; d < D_N; d += 256) {
        float4 a  = *(const float4*)(dirk + (size_t)d * 8);
        float4 b4 = *(const float4*)(dirk + (size_t)d * 8 + 4);
        ns[0] += a.x * a.x;  ns[1] += a.y * a.y;
        ns[2] += a.z * a.z;  ns[3] += a.w * a.w;
        ns[4] += b4.x * b4.x; ns[5] += b4.y * b4.y;
        ns[6] += b4.z * b4.z; ns[7] += b4.w * b4.w;
    }
#pragma unroll
    for (int j = 0; j < 8; j++) atomicAdd(&s_nsq[j], ns[j]);
    __syncthreads();
    if (tid < 8) {
        float sp = softplusf(scale_rho[k * 8 + tid]);
        s_alpha[tid] = sp / fmaxf(sqrtf(s_nsq[tid]), EPSC);
    }
    __syncthreads();
    float al[8];
#pragma unroll
    for (int j = 0; j < 8; j++) al[j] = s_alpha[j];

    // pass 2: S (36), wm (8), mumu; write Wcat columns
    float S[36], wm[8], mm = 0.0f;
#pragma unroll
    for (int i = 0; i < 36; i++) S[i] = 0.0f;
#pragma unroll
    for (int i = 0; i < 8; i++) wm[i] = 0.0f;

    for (int d = tid; d < D_N; d += 256) {
        float dv[8];
        float4 a  = *(const float4*)(dirk + (size_t)d * 8);
        float4 b4 = *(const float4*)(dirk + (size_t)d * 8 + 4);
        dv[0] = a.x; dv[1] = a.y; dv[2] = a.z; dv[3] = a.w;
        dv[4] = b4.x; dv[5] = b4.y; dv[6] = b4.z; dv[7] = b4.w;
        float pi = g_psi_inv[d];
        float m  = muk[d];
        float pim = pi * m;
        mm += m * pim;
        int idx = 0;
#pragma unroll
        for (int i = 0; i < 8; i++) {
            float pdi = pi * dv[i];
            wm[i] += m * pdi;
#pragma unroll
            for (int j = 0; j <= i; j++) S[idx++] += pdi * dv[j];
        }
        float* wrow = &g_Wcat[(size_t)d * NCOL];
        wrow[k] = pim;  // pm column
        float4 w0 = make_float4(pi * al[0] * dv[0], pi * al[1] * dv[1],
                                pi * al[2] * dv[2], pi * al[3] * dv[3]);
        float4 w1 = make_float4(pi * al[4] * dv[4], pi * al[5] * dv[5],
                                pi * al[6] * dv[6], pi * al[7] * dv[7]);
        *(float4*)&wrow[512 + k * 8]     = w0;
        *(float4*)&wrow[512 + k * 8 + 4] = w1;
    }
#pragma unroll
    for (int i = 0; i < 36; i++) atomicAdd(&s_acc[i], S[i]);
#pragma unroll
    for (int j = 0; j < 8; j++) atomicAdd(&s_acc[36 + j], wm[j]);
    atomicAdd(&s_acc[44], mm);
    __syncthreads();

    if (tid == 0) {
        // M = I + alpha_i alpha_j S_ij (lower)
        float Mm[8][8];
        int idx = 0;
        for (int i = 0; i < 8; i++)
            for (int j = 0; j <= i; j++) {
                Mm[i][j] = al[i] * al[j] * s_acc[idx++] + (i == j ? 1.0f : 0.0f);
            }
        // Cholesky (lower, in place)
        for (int i = 0; i < 8; i++) {
            for (int j = 0; j <= i; j++) {
                float s = Mm[i][j];
                for (int p = 0; p < j; p++) s -= Mm[i][p] * Mm[j][p];
                if (i == j) Mm[i][i] = sqrtf(s);
                else        Mm[i][j] = s / Mm[j][j];
            }
        }
        float ld = 0.0f;
        for (int i = 0; i < 8; i++) ld += logf(Mm[i][i]);
        g_logdetM[k] = 2.0f * ld;
        g_mumu[k]    = s_acc[44];
        for (int j = 0; j < 8; j++) g_wpm[k * 8 + j] = al[j] * s_acc[36 + j];
        // L^-1 by forward substitution, then Minv = L^-T L^-1
        float Li[8][8];
        for (int i = 0; i < 8; i++)
            for (int j = 0; j < 8; j++) Li[i][j] = 0.0f;
        for (int c = 0; c < 8; c++) {
            for (int i = c; i < 8; i++) {
                float s = (i == c) ? 1.0f : 0.0f;
                for (int p = c; p < i; p++) s -= Mm[i][p] * Li[p][c];
                Li[i][c] = s / Mm[i][i];
            }
        }
        for (int i = 0; i < 8; i++)
            for (int j = 0; j < 8; j++) {
                float s = 0.0f;
                for (int m2 = 0; m2 < 8; m2++) s += Li[m2][i] * Li[m2][j];
                g_Minv[(size_t)k * 64 + i * 8 + j] = s;
            }
    }
}

// ---------------- per-k offset (needs logdetPsi, logdetM, mumu, log_pi) -----
__global__ void k_off(const float* __restrict__ pi_logits) {
    __shared__ float buf[512];
    int t = threadIdx.x;
    float v = pi_logits[t];
    buf[t] = v;
    __syncthreads();
    for (int s = 256; s > 0; s >>= 1) {
        if (t < s) buf[t] = fmaxf(buf[t], buf[t + s]);
        __syncthreads();
    }
    float mx = buf[0];
    __syncthreads();
    buf[t] = expf(v - mx);
    __syncthreads();
    for (int s = 256; s > 0; s >>= 1) {
        if (t < s) buf[t] += buf[t + s];
        __syncthreads();
    }
    float lse = logf(buf[0]) + mx;
    g_off[t] = -0.5f * ((float)D_N * LOG2PI + g_logdetPsi + g_logdetM[t] + g_mumu[t])
               + v - lse;
}

// ---------------- r[b] = x^T Psi^-1 x ----------------
__global__ void k_xpx(const float* __restrict__ x) {
    int warp = threadIdx.x >> 5, lane = threadIdx.x & 31;
    int b = blockIdx.x * 8 + warp;
    const float* xb = x + (size_t)b * D_N;
    float s = 0.0f;
    for (int d = lane * 4; d < D_N; d += 128) {
        float4 xv = *(const float4*)(xb + d);
        float4 pv = *(const float4*)(g_psi_inv + d);
        s += xv.x * xv.x * pv.x + xv.y * xv.y * pv.y
           + xv.z * xv.z * pv.z + xv.w * xv.w * pv.w;
    }
    for (int o = 16; o; o >>= 1) s += __shfl_xor_sync(0xffffffffu, s, o);
    if (lane == 0) g_r[b] = s;
}

// ---------------- main GEMM: C = X (8192x2048) @ Wcat (2048x4608) -----------
#define BM 128
#define BN 128
#define BK 8
__global__ void __launch_bounds__(256, 2)
k_sgemm(const float* __restrict__ A) {
    __shared__ float As[BK][BM];
    __shared__ float Bs[BK][BN];
    int bx = blockIdx.x, by = blockIdx.y;
    int tid = threadIdx.x;
    int tx = tid & 15, ty = tid >> 4;
    const float* Ab = A + (size_t)by * BM * D_N;
    const float* Bb = g_Wcat + bx * BN;
    float acc[8][8];
#pragma unroll
    for (int i = 0; i < 8; i++)
#pragma unroll
        for (int j = 0; j < 8; j++) acc[i][j] = 0.0f;

    int arow = tid >> 1;
    int acol = (tid & 1) * 4;
    int brow = tid >> 5;
    int bcol = (tid & 31) * 4;

    for (int k0 = 0; k0 < D_N; k0 += BK) {
        float4 av = *(const float4*)(Ab + (size_t)arow * D_N + k0 + acol);
        As[acol + 0][arow] = av.x; As[acol + 1][arow] = av.y;
        As[acol + 2][arow] = av.z; As[acol + 3][arow] = av.w;
        float4 bv = *(const float4*)(Bb + (size_t)(k0 + brow) * NCOL + bcol);
        *(float4*)&Bs[brow][bcol] = bv;
        __syncthreads();
#pragma unroll
        for (int kk = 0; kk < BK; kk++) {
            float a[8], b[8];
#pragma unroll
            for (int i = 0; i < 8; i++) a[i] = As[kk][ty * 8 + i];
#pragma unroll
            for (int j = 0; j < 8; j++) b[j] = Bs[kk][tx * 8 + j];
#pragma unroll
            for (int i = 0; i < 8; i++)
#pragma unroll
                for (int j = 0; j < 8; j++) acc[i][j] += a[i] * b[j];
        }
        __syncthreads();
    }
#pragma unroll
    for (int i = 0; i < 8; i++) {
        float* crow = g_C + (size_t)(by * BM + ty * 8 + i) * NCOL + bx * BN + tx * 8;
        *(float4*)(crow)     = make_float4(acc[i][0], acc[i][1], acc[i][2], acc[i][3]);
        *(float4*)(crow + 4) = make_float4(acc[i][4], acc[i][5], acc[i][6], acc[i][7]);
    }
}

// ---------------- epilogue 1: s[b][k] = off + t1 + 0.5 v^T Minv v -----------
__global__ void k_e1() {
    __shared__ float sM[64 * 65];
    __shared__ float sW[64 * 9];
    __shared__ float sO[64];
    int k0 = blockIdx.x * 64, b0 = blockIdx.y * 64;
    int tid = threadIdx.x;
    for (int t = tid; t < 64 * 64; t += 256)
        sM[(t >> 6) * 65 + (t & 63)] = g_Minv[(size_t)(k0 + (t >> 6)) * 64 + (t & 63)];
    for (int t = tid; t < 64 * 8; t += 256)
        sW[(t >> 3) * 9 + (t & 7)] = g_wpm[(k0 + (t >> 3)) * 8 + (t & 7)];
    if (tid < 64) sO[tid] = g_off[k0 + tid];
    __syncthreads();
    int kl = tid & 63;
    int k  = k0 + kl;
    const float* Mv = &sM[kl * 65];
    const float* Wv = &sW[kl * 9];
    float off = sO[kl];
    for (int bb = tid >> 6; bb < 64; bb += 4) {
        size_t row = (size_t)(b0 + bb) * NCOL;
        float t1 = g_C[row + k];
        float4 v0 = *(const float4*)&g_C[row + 512 + k * 8];
        float4 v1 = *(const float4*)&g_C[row + 512 + k * 8 + 4];
        float v[8];
        v[0] = v0.x - Wv[0]; v[1] = v0.y - Wv[1];
        v[2] = v0.z - Wv[2]; v[3] = v0.w - Wv[3];
        v[4] = v1.x - Wv[4]; v[5] = v1.y - Wv[5];
        v[6] = v1.z - Wv[6]; v[7] = v1.w - Wv[7];
        float q = 0.0f;
#pragma unroll
        for (int i = 0; i < 8; i++) {
            float mi = 0.0f;
#pragma unroll
            for (int j = 0; j < 8; j++) mi += Mv[i * 8 + j] * v[j];
            q += v[i] * mi;
        }
        g_C[row + k] = off + t1 + 0.5f * q;
    }
}

// ---------------- epilogue 2: logsumexp over k, accumulate NLL --------------
__global__ void k_e2() {
    int warp = threadIdx.x >> 5, lane = threadIdx.x & 31;
    int b = blockIdx.x * 8 + warp;
    const float* row = &g_C[(size_t)b * NCOL];
    float vals[16];
    float mx = -1e30f;
#pragma unroll
    for (int i = 0; i < 16; i++) {
        vals[i] = row[i * 32 + lane];
        mx = fmaxf(mx, vals[i]);
    }
    for (int o = 16; o; o >>= 1) mx = fmaxf(mx, __shfl_xor_sync(0xffffffffu, mx, o));
    float s = 0.0f;
#pragma unroll
    for (int i = 0; i < 16; i++) s += expf(vals[i] - mx);
    for (int o = 16; o; o >>= 1) s += __shfl_xor_sync(0xffffffffu, s, o);
    if (lane == 0) {
        float logp = logf(s) + mx - 0.5f * g_r[b];
        atomicAdd(&g_acc, (double)(-logp));
    }
}

__global__ void k_init() { g_acc = 0.0; }
__global__ void k_fin(float* out) { out[0] = (float)(g_acc * (1.0 / (double)B_N)); }

// ---------------- launch ----------------
extern "C" void kernel_launch(void* const* d_in, const int* in_sizes, int n_in,
                              void* d_out, int out_size) {
    const float* x         = (const float*)d_in[0];
    const float* mu        = (const float*)d_in[1];
    const float* dir_raw   = (const float*)d_in[2];
    const float* scale_rho = (const float*)d_in[3];
    const float* psi_rho   = (const float*)d_in[4];
    const float* pi_logits = (const float*)d_in[5];
    float* out = (float*)d_out;

    k_init<<<1, 1>>>();
    k_psi<<<1, 256>>>(psi_rho);
    prep_k<<<K_N, 256>>>(dir_raw, mu, scale_rho);
    k_off<<<1, 512>>>(pi_logits);
    k_xpx<<<B_N / 8, 256>>>(x);
    dim3 gg(NCOL / BN, B_N / BM);
    k_sgemm<<<gg, 256>>>(x);
    k_e1<<<dim3(K_N / 64, B_N / 64), 256>>>();
    k_e2<<<B_N / 8, 256>>>();
    k_fin<<<1, 1>>>(out);
}

// round 3
// speedup vs baseline: 4.5249x; 4.5249x over previous
#include <cuda_runtime.h>
#include <cuda_bf16.h>
#include <math.h>
#include <stdint.h>

#define B_N    8192
#define K_N    512
#define D_N    2048
#define Q_N    8
#define NCOL   4608            // 512 (pm) + 512*8 (PinvW)
#define LOG2PI 1.8378770664093453f
#define EPSC   1e-5f

// ---------------- scratch (static __device__, no allocation) ----------------
__device__ __nv_bfloat16 g_XB[(size_t)B_N * D_N];   // X in bf16, 33.5 MB
__device__ __nv_bfloat16 g_WB[(size_t)NCOL * D_N];  // Wcat^T in bf16 [n][d], 18.9 MB
__device__ float  g_C[(size_t)B_N * NCOL];          // GEMM out, 151 MB
__device__ float  g_psi_inv[D_N];
__device__ float  g_logdetPsi;
__device__ float  g_r[B_N];                         // x^T Psi^-1 x
__device__ float  g_wpm[K_N * Q_N];                 // W^T Psi^-1 mu
__device__ float  g_Minv[K_N * 64];                 // full 8x8 M^-1 per k
__device__ float  g_logdetM[K_N];
__device__ float  g_mumu[K_N];
__device__ float  g_off[K_N];
__device__ double g_acc;

__device__ __forceinline__ float softplusf(float x) {
    return x > 20.0f ? x : log1pf(expf(x));
}
__device__ __forceinline__ uint32_t smem_u32(const void* p) {
    uint32_t a;
    asm("{ .reg .u64 t; cvta.to.shared.u64 t, %1; cvt.u32.u64 %0, t; }" : "=r"(a) : "l"(p));
    return a;
}
__device__ __forceinline__ void cp_async16(uint32_t saddr, const void* gaddr) {
    asm volatile("cp.async.cg.shared.global [%0], [%1], 16;" :: "r"(saddr), "l"(gaddr));
}
__device__ __forceinline__ void cp_commit() {
    asm volatile("cp.async.commit_group;");
}

// ---------------- psi precompute ----------------
__global__ void k_psi(const float* __restrict__ psi_rho) {
    __shared__ float ssum;
    int tid = threadIdx.x;
    if (tid == 0) ssum = 0.0f;
    __syncthreads();
    float l = 0.0f;
    for (int d = tid; d < D_N; d += 256) {
        float p = softplusf(psi_rho[d]) + EPSC;
        g_psi_inv[d] = 1.0f / p;
        l += logf(p);
    }
    atomicAdd(&ssum, l);
    __syncthreads();
    if (tid == 0) g_logdetPsi = ssum;
}

// ---------------- X -> bf16 ----------------
__global__ void k_cvt(const float* __restrict__ x) {
    size_t i = ((size_t)blockIdx.x * 256 + threadIdx.x) * 8;
    float4 a = *(const float4*)(x + i);
    float4 b = *(const float4*)(x + i + 4);
    __nv_bfloat162 p0 = __float22bfloat162_rn(make_float2(a.x, a.y));
    __nv_bfloat162 p1 = __float22bfloat162_rn(make_float2(a.z, a.w));
    __nv_bfloat162 p2 = __float22bfloat162_rn(make_float2(b.x, b.y));
    __nv_bfloat162 p3 = __float22bfloat162_rn(make_float2(b.z, b.w));
    uint4 o;
    o.x = *(uint32_t*)&p0; o.y = *(uint32_t*)&p1;
    o.z = *(uint32_t*)&p2; o.w = *(uint32_t*)&p3;
    *(uint4*)(g_XB + i) = o;
}

// ---------------- per-component precompute (one block per k) ----------------
__global__ void prep_k(const float* __restrict__ dir_raw,
                       const float* __restrict__ mu,
                       const float* __restrict__ scale_rho) {
    int k   = blockIdx.x;
    int tid = threadIdx.x;
    __shared__ float s_nsq[8];
    __shared__ float s_alpha[8];
    __shared__ float s_acc[45];
    if (tid < 8)  s_nsq[tid] = 0.0f;
    if (tid < 45) s_acc[tid] = 0.0f;
    __syncthreads();

    const float* dirk = dir_raw + (size_t)k * D_N * Q_N;
    const float* muk  = mu + (size_t)k * D_N;

    float ns[8];
#pragma unroll
    for (int j = 0; j < 8; j++) ns[j] = 0.0f;
    for (int d = tid; d < D_N; d += 256) {
        float4 a  = *(const float4*)(dirk + (size_t)d * 8);
        float4 b4 = *(const float4*)(dirk + (size_t)d * 8 + 4);
        ns[0] += a.x * a.x;  ns[1] += a.y * a.y;
        ns[2] += a.z * a.z;  ns[3] += a.w * a.w;
        ns[4] += b4.x * b4.x; ns[5] += b4.y * b4.y;
        ns[6] += b4.z * b4.z; ns[7] += b4.w * b4.w;
    }
#pragma unroll
    for (int j = 0; j < 8; j++) atomicAdd(&s_nsq[j], ns[j]);
    __syncthreads();
    if (tid < 8) {
        float sp = softplusf(scale_rho[k * 8 + tid]);
        s_alpha[tid] = sp / fmaxf(sqrtf(s_nsq[tid]), EPSC);
    }
    __syncthreads();
    float al[8];
#pragma unroll
    for (int j = 0; j < 8; j++) al[j] = s_alpha[j];

    float S[36], wm[8], mm = 0.0f;
#pragma unroll
    for (int i = 0; i < 36; i++) S[i] = 0.0f;
#pragma unroll
    for (int i = 0; i < 8; i++) wm[i] = 0.0f;

    for (int d = tid; d < D_N; d += 256) {
        float dv[8];
        float4 a  = *(const float4*)(dirk + (size_t)d * 8);
        float4 b4 = *(const float4*)(dirk + (size_t)d * 8 + 4);
        dv[0] = a.x; dv[1] = a.y; dv[2] = a.z; dv[3] = a.w;
        dv[4] = b4.x; dv[5] = b4.y; dv[6] = b4.z; dv[7] = b4.w;
        float pi = g_psi_inv[d];
        float m  = muk[d];
        float pim = pi * m;
        mm += m * pim;
        int idx = 0;
#pragma unroll
        for (int i = 0; i < 8; i++) {
            float pdi = pi * dv[i];
            wm[i] += m * pdi;
#pragma unroll
            for (int j = 0; j <= i; j++) S[idx++] += pdi * dv[j];
        }
        // write Wcat^T rows in bf16 (col-major B operand layout [n][d])
        g_WB[(size_t)k * D_N + d] = __float2bfloat16(pim);
#pragma unroll
        for (int j = 0; j < 8; j++) {
            g_WB[(size_t)(K_N + k * 8 + j) * D_N + d] = __float2bfloat16(pi * al[j] * dv[j]);
        }
    }
#pragma unroll
    for (int i = 0; i < 36; i++) atomicAdd(&s_acc[i], S[i]);
#pragma unroll
    for (int j = 0; j < 8; j++) atomicAdd(&s_acc[36 + j], wm[j]);
    atomicAdd(&s_acc[44], mm);
    __syncthreads();

    if (tid == 0) {
        float Mm[8][8];
        int idx = 0;
        for (int i = 0; i < 8; i++)
            for (int j = 0; j <= i; j++)
                Mm[i][j] = al[i] * al[j] * s_acc[idx++] + (i == j ? 1.0f : 0.0f);
        for (int i = 0; i < 8; i++) {
            for (int j = 0; j <= i; j++) {
                float s = Mm[i][j];
                for (int p = 0; p < j; p++) s -= Mm[i][p] * Mm[j][p];
                if (i == j) Mm[i][i] = sqrtf(s);
                else        Mm[i][j] = s / Mm[j][j];
            }
        }
        float ld = 0.0f;
        for (int i = 0; i < 8; i++) ld += logf(Mm[i][i]);
        g_logdetM[k] = 2.0f * ld;
        g_mumu[k]    = s_acc[44];
        for (int j = 0; j < 8; j++) g_wpm[k * 8 + j] = al[j] * s_acc[36 + j];
        float Li[8][8];
        for (int i = 0; i < 8; i++)
            for (int j = 0; j < 8; j++) Li[i][j] = 0.0f;
        for (int c = 0; c < 8; c++) {
            for (int i = c; i < 8; i++) {
                float s = (i == c) ? 1.0f : 0.0f;
                for (int p = c; p < i; p++) s -= Mm[i][p] * Li[p][c];
                Li[i][c] = s / Mm[i][i];
            }
        }
        for (int i = 0; i < 8; i++)
            for (int j = 0; j < 8; j++) {
                float s = 0.0f;
                for (int m2 = 0; m2 < 8; m2++) s += Li[m2][i] * Li[m2][j];
                g_Minv[(size_t)k * 64 + i * 8 + j] = s;
            }
    }
}

// ---------------- per-k offset ----------------
__global__ void k_off(const float* __restrict__ pi_logits) {
    __shared__ float buf[512];
    int t = threadIdx.x;
    float v = pi_logits[t];
    buf[t] = v;
    __syncthreads();
    for (int s = 256; s > 0; s >>= 1) {
        if (t < s) buf[t] = fmaxf(buf[t], buf[t + s]);
        __syncthreads();
    }
    float mx = buf[0];
    __syncthreads();
    buf[t] = expf(v - mx);
    __syncthreads();
    for (int s = 256; s > 0; s >>= 1) {
        if (t < s) buf[t] += buf[t + s];
        __syncthreads();
    }
    float lse = logf(buf[0]) + mx;
    g_off[t] = -0.5f * ((float)D_N * LOG2PI + g_logdetPsi + g_logdetM[t] + g_mumu[t])
               + v - lse;
}

// ---------------- r[b] = x^T Psi^-1 x ----------------
__global__ void k_xpx(const float* __restrict__ x) {
    int warp = threadIdx.x >> 5, lane = threadIdx.x & 31;
    int b = blockIdx.x * 8 + warp;
    const float* xb = x + (size_t)b * D_N;
    float s = 0.0f;
    for (int d = lane * 4; d < D_N; d += 128) {
        float4 xv = *(const float4*)(xb + d);
        float4 pv = *(const float4*)(g_psi_inv + d);
        s += xv.x * xv.x * pv.x + xv.y * xv.y * pv.y
           + xv.z * xv.z * pv.z + xv.w * xv.w * pv.w;
    }
    for (int o = 16; o; o >>= 1) s += __shfl_xor_sync(0xffffffffu, s, o);
    if (lane == 0) g_r[b] = s;
}

// ---------------- bf16 MMA GEMM: C = XB (8192x2048) @ WB^T ------------------
// CTA tile 128x128, BK=32, 3-stage cp.async pipeline, mma.sync m16n8k16.
#define BK       32
#define KBLOCKS  (D_N / BK)      // 64
#define STAGES   3
#define TILE_A   8192            // 128 rows * 64B
#define TILE_B   8192
#define TILE_AB  (TILE_A + TILE_B)

__global__ void __launch_bounds__(256, 2) k_mma_gemm() {
    __shared__ __align__(128) char smem[STAGES * TILE_AB];
    const int tid  = threadIdx.x;
    const int wid  = tid >> 5;
    const int lane = tid & 31;
    const int warp_m = wid & 1;    // 0..1 (64 rows each)
    const int warp_n = wid >> 1;   // 0..3 (32 cols each)
    const int bx = blockIdx.x;     // N tile (0..35)
    const int by = blockIdx.y;     // M tile (0..63)

    const uint32_t sbase = smem_u32(smem);
    const __nv_bfloat16* Ag = g_XB + (size_t)(by * 128) * D_N;
    const __nv_bfloat16* Bg = g_WB + (size_t)(bx * 128) * D_N;

    // issue cp.async loads for k-block kb into stage s
    auto load_stage = [&](int s, int kb) {
        uint32_t aB = sbase + s * TILE_AB;
        uint32_t bB = aB + TILE_A;
#pragma unroll
        for (int i = 0; i < 2; i++) {
            int id  = tid + i * 256;     // 0..511
            int row = id >> 2;
            int ch  = id & 3;            // 16B chunk (8 bf16)
            int sw  = ch ^ ((row >> 1) & 3);
            cp_async16(aB + row * 64 + sw * 16, Ag + (size_t)row * D_N + kb * BK + ch * 8);
            cp_async16(bB + row * 64 + sw * 16, Bg + (size_t)row * D_N + kb * BK + ch * 8);
        }
        cp_commit();
    };

    float acc[4][4][4];
#pragma unroll
    for (int mi = 0; mi < 4; mi++)
#pragma unroll
        for (int ni = 0; ni < 4; ni++)
#pragma unroll
            for (int j = 0; j < 4; j++) acc[mi][ni][j] = 0.0f;

    load_stage(0, 0);
    load_stage(1, 1);
    load_stage(2, 2);

    for (int kb = 0; kb < KBLOCKS; kb++) {
        asm volatile("cp.async.wait_group 2;");
        __syncthreads();
        int s = kb % STAGES;
        uint32_t aB = sbase + s * TILE_AB;
        uint32_t bB = aB + TILE_A;
#pragma unroll
        for (int ks = 0; ks < 2; ks++) {
            uint32_t a[4][4], b[4][2];
#pragma unroll
            for (int mi = 0; mi < 4; mi++) {
                int r  = warp_m * 64 + mi * 16 + (lane & 15);
                int ch = ks * 2 + (lane >> 4);
                uint32_t ad = aB + r * 64 + ((ch ^ ((r >> 1) & 3)) * 16);
                asm volatile("ldmatrix.sync.aligned.m8n8.x4.shared.b16 {%0,%1,%2,%3}, [%4];"
                             : "=r"(a[mi][0]), "=r"(a[mi][1]), "=r"(a[mi][2]), "=r"(a[mi][3])
                             : "r"(ad));
            }
            int c = lane & 15;
#pragma unroll
            for (int ni = 0; ni < 4; ni++) {
                int r  = warp_n * 32 + ni * 8 + (c & 7);
                int ch = ks * 2 + (c >> 3);
                uint32_t bd = bB + r * 64 + ((ch ^ ((r >> 1) & 3)) * 16);
                asm volatile("ldmatrix.sync.aligned.m8n8.x2.shared.b16 {%0,%1}, [%2];"
                             : "=r"(b[ni][0]), "=r"(b[ni][1]) : "r"(bd));
            }
#pragma unroll
            for (int mi = 0; mi < 4; mi++)
#pragma unroll
                for (int ni = 0; ni < 4; ni++) {
                    asm volatile(
                        "mma.sync.aligned.m16n8k16.row.col.f32.bf16.bf16.f32 "
                        "{%0,%1,%2,%3}, {%4,%5,%6,%7}, {%8,%9}, {%0,%1,%2,%3};"
                        : "+f"(acc[mi][ni][0]), "+f"(acc[mi][ni][1]),
                          "+f"(acc[mi][ni][2]), "+f"(acc[mi][ni][3])
                        : "r"(a[mi][0]), "r"(a[mi][1]), "r"(a[mi][2]), "r"(a[mi][3]),
                          "r"(b[ni][0]), "r"(b[ni][1]));
                }
        }
        __syncthreads();
        if (kb + STAGES < KBLOCKS) load_stage(s, kb + STAGES);
    }

    // epilogue: write fragments to g_C
    int gq = lane >> 2;        // group id 0..7
    int tg = lane & 3;         // thread in group
#pragma unroll
    for (int mi = 0; mi < 4; mi++) {
        int r0 = by * 128 + warp_m * 64 + mi * 16 + gq;
        int r1 = r0 + 8;
#pragma unroll
        for (int ni = 0; ni < 4; ni++) {
            int col = bx * 128 + warp_n * 32 + ni * 8 + tg * 2;
            *(float2*)&g_C[(size_t)r0 * NCOL + col] = make_float2(acc[mi][ni][0], acc[mi][ni][1]);
            *(float2*)&g_C[(size_t)r1 * NCOL + col] = make_float2(acc[mi][ni][2], acc[mi][ni][3]);
        }
    }
}

// ---------------- epilogue 1: s[b][k] = off + t1 + 0.5 v^T Minv v -----------
__global__ void k_e1() {
    __shared__ float sM[64 * 65];
    __shared__ float sW[64 * 9];
    __shared__ float sO[64];
    int k0 = blockIdx.x * 64, b0 = blockIdx.y * 64;
    int tid = threadIdx.x;
    for (int t = tid; t < 64 * 64; t += 256)
        sM[(t >> 6) * 65 + (t & 63)] = g_Minv[(size_t)(k0 + (t >> 6)) * 64 + (t & 63)];
    for (int t = tid; t < 64 * 8; t += 256)
        sW[(t >> 3) * 9 + (t & 7)] = g_wpm[(k0 + (t >> 3)) * 8 + (t & 7)];
    if (tid < 64) sO[tid] = g_off[k0 + tid];
    __syncthreads();
    int kl = tid & 63;
    int k  = k0 + kl;
    const float* Mv = &sM[kl * 65];
    const float* Wv = &sW[kl * 9];
    float off = sO[kl];
    for (int bb = tid >> 6; bb < 64; bb += 4) {
        size_t row = (size_t)(b0 + bb) * NCOL;
        float t1 = g_C[row + k];
        float4 v0 = *(const float4*)&g_C[row + 512 + k * 8];
        float4 v1 = *(const float4*)&g_C[row + 512 + k * 8 + 4];
        float v[8];
        v[0] = v0.x - Wv[0]; v[1] = v0.y - Wv[1];
        v[2] = v0.z - Wv[2]; v[3] = v0.w - Wv[3];
        v[4] = v1.x - Wv[4]; v[5] = v1.y - Wv[5];
        v[6] = v1.z - Wv[6]; v[7] = v1.w - Wv[7];
        float q = 0.0f;
#pragma unroll
        for (int i = 0; i < 8; i++) {
            float mi = 0.0f;
#pragma unroll
            for (int j = 0; j < 8; j++) mi += Mv[i * 8 + j] * v[j];
            q += v[i] * mi;
        }
        g_C[row + k] = off + t1 + 0.5f * q;
    }
}

// ---------------- epilogue 2: logsumexp over k, accumulate NLL --------------
__global__ void k_e2() {
    int warp = threadIdx.x >> 5, lane = threadIdx.x & 31;
    int b = blockIdx.x * 8 + warp;
    const float* row = &g_C[(size_t)b * NCOL];
    float vals[16];
    float mx = -1e30f;
#pragma unroll
    for (int i = 0; i < 16; i++) {
        vals[i] = row[i * 32 + lane];
        mx = fmaxf(mx, vals[i]);
    }
    for (int o = 16; o; o >>= 1) mx = fmaxf(mx, __shfl_xor_sync(0xffffffffu, mx, o));
    float s = 0.0f;
#pragma unroll
    for (int i = 0; i < 16; i++) s += expf(vals[i] - mx);
    for (int o = 16; o; o >>= 1) s += __shfl_xor_sync(0xffffffffu, s, o);
    if (lane == 0) {
        float logp = logf(s) + mx - 0.5f * g_r[b];
        atomicAdd(&g_acc, (double)(-logp));
    }
}

__global__ void k_init() { g_acc = 0.0; }
__global__ void k_fin(float* out) { out[0] = (float)(g_acc * (1.0 / (double)B_N)); }

// ---------------- launch ----------------
extern "C" void kernel_launch(void* const* d_in, const int* in_sizes, int n_in,
                              void* d_out, int out_size) {
    const float* x         = (const float*)d_in[0];
    const float* mu        = (const float*)d_in[1];
    const float* dir_raw   = (const float*)d_in[2];
    const float* scale_rho = (const float*)d_in[3];
    const float* psi_rho   = (const float*)d_in[4];
    const float* pi_logits = (const float*)d_in[5];
    float* out = (float*)d_out;

    k_init<<<1, 1>>>();
    k_psi<<<1, 256>>>(psi_rho);
    k_cvt<<<(B_N * D_N) / (256 * 8), 256>>>(x);
    prep_k<<<K_N, 256>>>(dir_raw, mu, scale_rho);
    k_off<<<1, 512>>>(pi_logits);
    k_xpx<<<B_N / 8, 256>>>(x);
    dim3 gg(NCOL / 128, B_N / 128);
    k_mma_gemm<<<gg, 256>>>();
    k_e1<<<dim3(K_N / 64, B_N / 64), 256>>>();
    k_e2<<<B_N / 8, 256>>>();
    k_fin<<<1, 1>>>(out);
}